// round 2
// baseline (speedup 1.0000x reference)
#include <cuda_runtime.h>
#include <cstdint>
#include <math.h>

#define NN 8192
#define DD 128
#define NE (NN*3)

// ---------------- device scratch (no allocations allowed) ----------------
__device__ float g_sq[NN];
__device__ unsigned long long g_cand[2ull*NN*16*3];
__device__ int g_nbr[NE];
__device__ float g_xp[(size_t)NN*256];    // x @ W, [N][H=2][128]
__device__ float g_as[NN*2];
__device__ float g_ad[NN*2];
__device__ unsigned g_menc[NN*2];
__device__ float g_denom[NN*2];
__device__ float g_w[NE*2];
__device__ float g_acc[(size_t)NN*256];   // aggregated messages [N][H][128]

__device__ __forceinline__ unsigned encf(float f){
  unsigned u = __float_as_uint(f);
  return (u & 0x80000000u) ? ~u : (u | 0x80000000u);
}
__device__ __forceinline__ float decf(unsigned u){
  return (u & 0x80000000u) ? __uint_as_float(u ^ 0x80000000u) : __uint_as_float(~u);
}
__device__ __forceinline__ void ins3(unsigned long long k,
                                     unsigned long long &b0,
                                     unsigned long long &b1,
                                     unsigned long long &b2){
  if (k < b2){
    if (k < b1){
      b2 = b1;
      if (k < b0){ b1 = b0; b0 = k; } else { b1 = k; }
    } else { b2 = k; }
  }
}

// ---------------- k1: row squared norms (warp per row) ----------------
__global__ void k_sqnorm(const float4* __restrict__ X4){
  int g = blockIdx.x*blockDim.x + threadIdx.x;
  int row = g >> 5, lane = g & 31;
  if (row >= NN) return;
  float4 v = X4[row*32 + lane];
  float s = v.x*v.x + v.y*v.y + v.z*v.z + v.w*v.w;
  #pragma unroll
  for (int o = 16; o; o >>= 1) s += __shfl_xor_sync(0xffffffffu, s, o);
  if (lane == 0) g_sq[row] = s;
}

// ---------------- k2: fused fp32 x@x^T + running top-3 ----------------
// grid 128 = 64 i-blocks x 2 j-splits. 256 thr (16x16), 8x8 frags, Kc=32.
__global__ __launch_bounds__(256) void k_knn(const float* __restrict__ X){
  __shared__ float sA[32*129];
  __shared__ float sB[32*129];
  __shared__ float sqs[128];
  const float4* X4 = (const float4*)X;
  int tid = threadIdx.x;
  int tx = tid & 15, ty = tid >> 4;
  int ib = blockIdx.x >> 1, split = blockIdx.x & 1;
  int i0 = ib*128;

  float sqi[8];
  #pragma unroll
  for (int m = 0; m < 8; m++) sqi[m] = g_sq[i0 + ty + 16*m];

  unsigned long long best[8][3];
  #pragma unroll
  for (int m = 0; m < 8; m++){ best[m][0] = ~0ull; best[m][1] = ~0ull; best[m][2] = ~0ull; }

  for (int jt = 0; jt < 32; jt++){
    int j0 = split*4096 + jt*128;
    float acc[8][8];
    #pragma unroll
    for (int a = 0; a < 8; a++)
      #pragma unroll
      for (int b = 0; b < 8; b++) acc[a][b] = 0.f;

    for (int kc = 0; kc < 4; kc++){
      __syncthreads();
      #pragma unroll
      for (int l = 0; l < 4; l++){
        int idx = tid + l*256;
        int r = idx >> 3, k4 = idx & 7;
        float4 va = X4[(i0 + r)*32 + kc*8 + k4];
        sA[(k4*4+0)*129 + r] = va.x;
        sA[(k4*4+1)*129 + r] = va.y;
        sA[(k4*4+2)*129 + r] = va.z;
        sA[(k4*4+3)*129 + r] = va.w;
        float4 vb = X4[(j0 + r)*32 + kc*8 + k4];
        sB[(k4*4+0)*129 + r] = vb.x;
        sB[(k4*4+1)*129 + r] = vb.y;
        sB[(k4*4+2)*129 + r] = vb.z;
        sB[(k4*4+3)*129 + r] = vb.w;
      }
      if (kc == 0 && tid < 128) sqs[tid] = g_sq[j0 + tid];
      __syncthreads();
      #pragma unroll 4
      for (int k = 0; k < 32; k++){
        float a[8], b[8];
        #pragma unroll
        for (int m = 0; m < 8; m++) a[m] = sA[k*129 + ty + 16*m];
        #pragma unroll
        for (int m = 0; m < 8; m++) b[m] = sB[k*129 + tx + 16*m];
        #pragma unroll
        for (int mi = 0; mi < 8; mi++)
          #pragma unroll
          for (int mj = 0; mj < 8; mj++)
            acc[mi][mj] = fmaf(a[mi], b[mj], acc[mi][mj]);
      }
    }
    #pragma unroll
    for (int mi = 0; mi < 8; mi++){
      float si = sqi[mi];
      #pragma unroll
      for (int mj = 0; mj < 8; mj++){
        int j = j0 + tx + 16*mj;
        float d2 = (si + sqs[tx + 16*mj]) - 2.0f*acc[mi][mj];
        unsigned long long key = ((unsigned long long)encf(d2) << 32) | (unsigned)j;
        ins3(key, best[mi][0], best[mi][1], best[mi][2]);
      }
    }
  }
  #pragma unroll
  for (int m = 0; m < 8; m++){
    int row = i0 + ty + 16*m;
    size_t base = ((size_t)(split*NN + row)*16 + tx)*3;
    g_cand[base+0] = best[m][0];
    g_cand[base+1] = best[m][1];
    g_cand[base+2] = best[m][2];
  }
}

// ---------------- k3: merge partial top-3 (warp per row) ----------------
__global__ void k_merge(){
  int g = blockIdx.x*blockDim.x + threadIdx.x;
  int row = g >> 5, lane = g & 31;
  if (row >= NN) return;
  int split = lane >> 4, tx = lane & 15;
  size_t base = ((size_t)(split*NN + row)*16 + tx)*3;
  unsigned long long b0 = g_cand[base+0];
  unsigned long long b1 = g_cand[base+1];
  unsigned long long b2 = g_cand[base+2];
  #pragma unroll
  for (int o = 16; o; o >>= 1){
    unsigned long long c0 = __shfl_xor_sync(0xffffffffu, b0, o);
    unsigned long long c1 = __shfl_xor_sync(0xffffffffu, b1, o);
    unsigned long long c2 = __shfl_xor_sync(0xffffffffu, b2, o);
    ins3(c0, b0, b1, b2);
    ins3(c1, b0, b1, b2);
    ins3(c2, b0, b1, b2);
  }
  if (lane == 0){
    g_nbr[row*3+0] = (int)(b0 & 0xffffffffull);
    g_nbr[row*3+1] = (int)(b1 & 0xffffffffull);
    g_nbr[row*3+2] = (int)(b2 & 0xffffffffull);
  }
}

// ---------------- k4: xp = x @ W (grid 128 = 64 ib x 2 heads) ----------------
__global__ __launch_bounds__(256) void k_xp(const float* __restrict__ X,
                                            const float* __restrict__ W){
  __shared__ float sA[32*129];
  __shared__ float sW[32*129];
  const float4* X4 = (const float4*)X;
  const float4* W4 = (const float4*)W;
  int tid = threadIdx.x;
  int tx = tid & 15, ty = tid >> 4;
  int ib = blockIdx.x >> 1, h = blockIdx.x & 1;
  int i0 = ib*128;
  float acc[8][8];
  #pragma unroll
  for (int a = 0; a < 8; a++)
    #pragma unroll
    for (int b = 0; b < 8; b++) acc[a][b] = 0.f;

  for (int kc = 0; kc < 4; kc++){
    __syncthreads();
    #pragma unroll
    for (int l = 0; l < 4; l++){
      int idx = tid + l*256;
      int r = idx >> 3, k4 = idx & 7;
      float4 va = X4[(i0 + r)*32 + kc*8 + k4];
      sA[(k4*4+0)*129 + r] = va.x;
      sA[(k4*4+1)*129 + r] = va.y;
      sA[(k4*4+2)*129 + r] = va.z;
      sA[(k4*4+3)*129 + r] = va.w;
      int dd = idx >> 5, c4 = idx & 31;
      float4 vw = W4[(size_t)(kc*32 + dd)*64 + h*32 + c4];
      sW[dd*129 + c4*4 + 0] = vw.x;
      sW[dd*129 + c4*4 + 1] = vw.y;
      sW[dd*129 + c4*4 + 2] = vw.z;
      sW[dd*129 + c4*4 + 3] = vw.w;
    }
    __syncthreads();
    #pragma unroll 4
    for (int k = 0; k < 32; k++){
      float a[8], b[8];
      #pragma unroll
      for (int m = 0; m < 8; m++) a[m] = sA[k*129 + ty + 16*m];
      #pragma unroll
      for (int m = 0; m < 8; m++) b[m] = sW[k*129 + tx + 16*m];
      #pragma unroll
      for (int mi = 0; mi < 8; mi++)
        #pragma unroll
        for (int mj = 0; mj < 8; mj++)
          acc[mi][mj] = fmaf(a[mi], b[mj], acc[mi][mj]);
    }
  }
  #pragma unroll
  for (int mi = 0; mi < 8; mi++)
    #pragma unroll
    for (int mj = 0; mj < 8; mj++)
      g_xp[(size_t)(i0 + ty + 16*mi)*256 + h*128 + tx + 16*mj] = acc[mi][mj];
}

// ---------------- k5: attention coeffs + init m/denom/acc ----------------
__global__ void k_attn(const float* __restrict__ att_src,
                       const float* __restrict__ att_dst){
  int g = blockIdx.x*blockDim.x + threadIdx.x;
  int n = g >> 5, lane = g & 31;
  if (n >= NN) return;
  const float4* xp4 = (const float4*)g_xp;
  float4 x0 = xp4[(size_t)n*64 + lane];
  float4 x1 = xp4[(size_t)n*64 + 32 + lane];
  const float4* s4 = (const float4*)att_src;
  const float4* d4 = (const float4*)att_dst;
  float4 a0 = s4[lane], a1 = s4[32 + lane];
  float4 c0 = d4[lane], c1 = d4[32 + lane];
  float vs0 = x0.x*a0.x + x0.y*a0.y + x0.z*a0.z + x0.w*a0.w;
  float vs1 = x1.x*a1.x + x1.y*a1.y + x1.z*a1.z + x1.w*a1.w;
  float vd0 = x0.x*c0.x + x0.y*c0.y + x0.z*c0.z + x0.w*c0.w;
  float vd1 = x1.x*c1.x + x1.y*c1.y + x1.z*c1.z + x1.w*c1.w;
  #pragma unroll
  for (int o = 16; o; o >>= 1){
    vs0 += __shfl_xor_sync(0xffffffffu, vs0, o);
    vs1 += __shfl_xor_sync(0xffffffffu, vs1, o);
    vd0 += __shfl_xor_sync(0xffffffffu, vd0, o);
    vd1 += __shfl_xor_sync(0xffffffffu, vd1, o);
  }
  if (lane == 0){
    g_as[n*2+0] = vs0; g_as[n*2+1] = vs1;
    g_ad[n*2+0] = vd0; g_ad[n*2+1] = vd1;
    g_menc[n*2+0] = 0x007FFFFFu;   // enc(-inf)
    g_menc[n*2+1] = 0x007FFFFFu;
    g_denom[n*2+0] = 0.f; g_denom[n*2+1] = 0.f;
  }
  float4 z = make_float4(0.f, 0.f, 0.f, 0.f);
  ((float4*)g_acc)[(size_t)n*64 + lane] = z;
  ((float4*)g_acc)[(size_t)n*64 + 32 + lane] = z;
}

// ---------------- k6: segment max ----------------
__global__ void k_emax(){
  int idx = blockIdx.x*blockDim.x + threadIdx.x;
  if (idx >= NE*2) return;
  int e = idx >> 1, h = idx & 1;
  int s = e/3;
  int d = g_nbr[e];
  float v = g_as[s*2+h] + g_ad[d*2+h];
  v = v > 0.f ? v : 0.2f*v;
  atomicMax(&g_menc[d*2+h], encf(v));
}

// ---------------- k7: exp + segment sum ----------------
__global__ void k_esum(){
  int idx = blockIdx.x*blockDim.x + threadIdx.x;
  if (idx >= NE*2) return;
  int e = idx >> 1, h = idx & 1;
  int s = e/3;
  int d = g_nbr[e];
  float v = g_as[s*2+h] + g_ad[d*2+h];
  v = v > 0.f ? v : 0.2f*v;
  float m = decf(g_menc[d*2+h]);
  float w = __expf(v - m);
  g_w[idx] = w;
  atomicAdd(&g_denom[d*2+h], w);
}

// ---------------- k8: aggregate messages (warp per edge-head) ----------------
__global__ void k_agg(){
  int g = blockIdx.x*blockDim.x + threadIdx.x;
  int eh = g >> 5, lane = g & 31;
  if (eh >= NE*2) return;
  int e = eh >> 1, h = eh & 1;
  int s = e/3;
  int d = g_nbr[e];
  float alpha = g_w[eh] / g_denom[d*2+h];
  const float4* xp4 = (const float4*)g_xp;
  float4 v = xp4[(size_t)s*64 + h*32 + lane];
  float* dst = &g_acc[(size_t)d*256 + h*128 + lane*4];
  atomicAdd(dst+0, alpha*v.x);
  atomicAdd(dst+1, alpha*v.y);
  atomicAdd(dst+2, alpha*v.z);
  atomicAdd(dst+3, alpha*v.w);
}

// ---------------- k9: head-mean + bias + LayerNorm + ReLU + residual ----------------
__global__ void k_final(const float* __restrict__ X,
                        const float* __restrict__ bias,
                        const float* __restrict__ gamma,
                        const float* __restrict__ beta,
                        float* __restrict__ out){
  int g = blockIdx.x*blockDim.x + threadIdx.x;
  int n = g >> 5, lane = g & 31;
  if (n >= NN) return;
  float v[4];
  #pragma unroll
  for (int c = 0; c < 4; c++){
    int dd = lane*4 + c;
    float a0 = g_acc[(size_t)n*256 + dd];
    float a1 = g_acc[(size_t)n*256 + 128 + dd];
    v[c] = 0.5f*(a0 + a1) + bias[dd];
  }
  float s = v[0]+v[1]+v[2]+v[3];
  #pragma unroll
  for (int o = 16; o; o >>= 1) s += __shfl_xor_sync(0xffffffffu, s, o);
  float mu = s * (1.0f/128.0f);
  float q = 0.f;
  #pragma unroll
  for (int c = 0; c < 4; c++){ float t = v[c]-mu; q += t*t; }
  #pragma unroll
  for (int o = 16; o; o >>= 1) q += __shfl_xor_sync(0xffffffffu, q, o);
  float rstd = rsqrtf(q*(1.0f/128.0f) + 1e-5f);
  #pragma unroll
  for (int c = 0; c < 4; c++){
    int dd = lane*4 + c;
    float y = (v[c]-mu)*rstd*gamma[dd] + beta[dd];
    y = y > 0.f ? y : 0.f;
    out[(size_t)n*128 + dd] = X[(size_t)n*128 + dd] + y;
  }
}

// ---------------- launch ----------------
extern "C" void kernel_launch(void* const* d_in, const int* in_sizes, int n_in,
                              void* d_out, int out_size) {
  const float* prototypes = (const float*)d_in[0];
  // d_in[1] = labels (unused in forward)
  const float* W       = (const float*)d_in[2];
  const float* att_src = (const float*)d_in[3];
  const float* att_dst = (const float*)d_in[4];
  const float* bias    = (const float*)d_in[5];
  const float* gamma   = (const float*)d_in[6];
  const float* beta    = (const float*)d_in[7];
  float* out = (float*)d_out;

  k_sqnorm<<<NN/8, 256>>>((const float4*)prototypes);
  k_knn<<<128, 256>>>(prototypes);
  k_merge<<<NN/8, 256>>>();
  k_xp<<<128, 256>>>(prototypes, W);
  k_attn<<<NN/8, 256>>>(att_src, att_dst);
  k_emax<<<(NE*2+255)/256, 256>>>();
  k_esum<<<(NE*2+255)/256, 256>>>();
  k_agg<<<(NE*2*32+255)/256, 256>>>();
  k_final<<<NN/8, 256>>>(prototypes, bias, gamma, beta, out);
}

// round 3
// speedup vs baseline: 1.2005x; 1.2005x over previous
#include <cuda_runtime.h>
#include <cstdint>
#include <math.h>

#define NN 8192
#define DD 128
#define NE (NN*3)

// ---------------- device scratch (no allocations allowed) ----------------
__device__ float g_sq[NN];
__device__ unsigned long long g_cand[2ull*NN*16*3];
__device__ int g_nbr[NE];
__device__ float g_xp[(size_t)NN*256];    // x @ W, [N][H=2][128]
__device__ float g_as[NN*2];
__device__ float g_ad[NN*2];
__device__ unsigned g_menc[NN*2];
__device__ float g_denom[NN*2];
__device__ float g_w[NE*2];
__device__ float g_acc[(size_t)NN*256];   // aggregated messages [N][H][128]

__device__ __forceinline__ unsigned encf(float f){
  unsigned u = __float_as_uint(f);
  return (u & 0x80000000u) ? ~u : (u | 0x80000000u);
}
__device__ __forceinline__ float decf(unsigned u){
  return (u & 0x80000000u) ? __uint_as_float(u ^ 0x80000000u) : __uint_as_float(~u);
}
__device__ __forceinline__ void ins3(unsigned long long k,
                                     unsigned long long &b0,
                                     unsigned long long &b1,
                                     unsigned long long &b2){
  if (k < b2){
    if (k < b1){
      b2 = b1;
      if (k < b0){ b1 = b0; b0 = k; } else { b1 = k; }
    } else { b2 = k; }
  }
}

// ---- packed f32x2 helpers (Blackwell FFMA2 path; ptxas never auto-emits) ----
__device__ __forceinline__ void ffma2(unsigned long long &d, unsigned long long a, unsigned long long b){
  asm("fma.rn.f32x2 %0, %1, %2, %0;" : "+l"(d) : "l"(a), "l"(b));
}
__device__ __forceinline__ unsigned long long dup2f(float x){
  unsigned long long r; unsigned u = __float_as_uint(x);
  asm("mov.b64 %0, {%1, %1};" : "=l"(r) : "r"(u));
  return r;
}
__device__ __forceinline__ unsigned long long pack2f(float lo, float hi){
  unsigned long long r;
  unsigned a = __float_as_uint(lo), b = __float_as_uint(hi);
  asm("mov.b64 %0, {%1, %2};" : "=l"(r) : "r"(a), "r"(b));
  return r;
}
__device__ __forceinline__ void unpack2f(unsigned long long v, float &lo, float &hi){
  unsigned a, b;
  asm("mov.b64 {%0, %1}, %2;" : "=r"(a), "=r"(b) : "l"(v));
  lo = __uint_as_float(a); hi = __uint_as_float(b);
}

// ---------------- k1: row squared norms (warp per row) ----------------
__global__ void k_sqnorm(const float4* __restrict__ X4){
  int g = blockIdx.x*blockDim.x + threadIdx.x;
  int row = g >> 5, lane = g & 31;
  if (row >= NN) return;
  float4 v = X4[row*32 + lane];
  float s = v.x*v.x + v.y*v.y + v.z*v.z + v.w*v.w;
  #pragma unroll
  for (int o = 16; o; o >>= 1) s += __shfl_xor_sync(0xffffffffu, s, o);
  if (lane == 0) g_sq[row] = s;
}

// ---------------- k2: fused fp32 x@x^T + running top-3 (f32x2 FFMA2) ----------------
// grid 128 = 64 i-blocks x 2 j-splits. Block 512 (tx=tid&15 col group, ty=tid>>4 row
// group). Frags 4 rows x 8 cols, accumulators packed f32x2 along col pairs.
// smem: full-K tiles, 16B-chunk layout with XOR swizzle: element (k,r) at
// word k*128 + ((r>>2)^(k>>2))*4 + (r&3). A loaded once; B double-buffered
// with register prefetch (one __syncthreads per j-tile).
__global__ __launch_bounds__(512, 1) void k_knn(const float* __restrict__ X){
  extern __shared__ float smem[];
  float* sA  = smem;              // 16384 floats
  float* sB0 = smem + 16384;
  float* sB1 = smem + 32768;
  const float4* X4 = (const float4*)X;
  int tid = threadIdx.x;
  int tx = tid & 15, ty = tid >> 4;          // ty 0..31
  int ib = blockIdx.x >> 1, split = blockIdx.x & 1;
  int i0 = ib*128;

  // prologue: A tile + B tile 0 into swizzled smem
  #pragma unroll
  for (int l = 0; l < 8; l++){
    int idx = tid + l*512;
    int r = idx >> 5, k4 = idx & 31;
    float4 v = X4[(size_t)(i0 + r)*32 + k4];
    float* p = sA + k4*4*128 + (((r>>2) ^ k4) << 2) + (r & 3);
    p[0] = v.x; p[128] = v.y; p[256] = v.z; p[384] = v.w;
  }
  {
    int j0 = split*4096;
    #pragma unroll
    for (int l = 0; l < 8; l++){
      int idx = tid + l*512;
      int r = idx >> 5, k4 = idx & 31;
      float4 v = X4[(size_t)(j0 + r)*32 + k4];
      float* p = sB0 + k4*4*128 + (((r>>2) ^ k4) << 2) + (r & 3);
      p[0] = v.x; p[128] = v.y; p[256] = v.z; p[384] = v.w;
    }
  }
  __syncthreads();

  float sqi[4];
  #pragma unroll
  for (int m = 0; m < 4; m++) sqi[m] = g_sq[i0 + ty*4 + m];

  unsigned long long best[4][3];
  #pragma unroll
  for (int m = 0; m < 4; m++){ best[m][0] = ~0ull; best[m][1] = ~0ull; best[m][2] = ~0ull; }

  const float4* sA4 = (const float4*)sA;

  for (int jt = 0; jt < 32; jt++){
    const float4* sB4 = (const float4*)((jt & 1) ? sB1 : sB0);
    float* sBn = (jt & 1) ? sB0 : sB1;
    int j0c = split*4096 + jt*128;

    float4 pf[8];
    if (jt < 31){
      int j0n = j0c + 128;
      #pragma unroll
      for (int l = 0; l < 8; l++){
        int idx = tid + l*512;
        int r = idx >> 5, k4 = idx & 31;
        pf[l] = X4[(size_t)(j0n + r)*32 + k4];
      }
    }

    unsigned long long acc[4][4];
    #pragma unroll
    for (int a = 0; a < 4; a++)
      #pragma unroll
      for (int b = 0; b < 4; b++) acc[a][b] = 0ull;

    #pragma unroll 2
    for (int kg = 0; kg < 16; kg++){
      int ca = ty ^ kg, c0 = tx ^ kg, c1 = (16 + tx) ^ kg;
      const float4* pA = sA4 + kg*128;
      const float4* pB = sB4 + kg*128;
      #pragma unroll
      for (int c = 0; c < 4; c++){
        float4 av = pA[c*32 + ca];
        float4 b0 = pB[c*32 + c0];
        float4 b1 = pB[c*32 + c1];
        unsigned long long bp[4];
        bp[0] = pack2f(b0.x, b0.y); bp[1] = pack2f(b0.z, b0.w);
        bp[2] = pack2f(b1.x, b1.y); bp[3] = pack2f(b1.z, b1.w);
        unsigned long long ad[4];
        ad[0] = dup2f(av.x); ad[1] = dup2f(av.y); ad[2] = dup2f(av.z); ad[3] = dup2f(av.w);
        #pragma unroll
        for (int mi = 0; mi < 4; mi++)
          #pragma unroll
          for (int jp = 0; jp < 4; jp++)
            ffma2(acc[mi][jp], ad[mi], bp[jp]);
      }
    }

    if (jt < 31){
      #pragma unroll
      for (int l = 0; l < 8; l++){
        int idx = tid + l*512;
        int r = idx >> 5, k4 = idx & 31;
        float* p = sBn + k4*4*128 + (((r>>2) ^ k4) << 2) + (r & 3);
        p[0] = pf[l].x; p[128] = pf[l].y; p[256] = pf[l].z; p[384] = pf[l].w;
      }
    }

    #pragma unroll 2
    for (int kg = 16; kg < 32; kg++){
      int ca = ty ^ kg, c0 = tx ^ kg, c1 = (16 + tx) ^ kg;
      const float4* pA = sA4 + kg*128;
      const float4* pB = sB4 + kg*128;
      #pragma unroll
      for (int c = 0; c < 4; c++){
        float4 av = pA[c*32 + ca];
        float4 b0 = pB[c*32 + c0];
        float4 b1 = pB[c*32 + c1];
        unsigned long long bp[4];
        bp[0] = pack2f(b0.x, b0.y); bp[1] = pack2f(b0.z, b0.w);
        bp[2] = pack2f(b1.x, b1.y); bp[3] = pack2f(b1.z, b1.w);
        unsigned long long ad[4];
        ad[0] = dup2f(av.x); ad[1] = dup2f(av.y); ad[2] = dup2f(av.z); ad[3] = dup2f(av.w);
        #pragma unroll
        for (int mi = 0; mi < 4; mi++)
          #pragma unroll
          for (int jp = 0; jp < 4; jp++)
            ffma2(acc[mi][jp], ad[mi], bp[jp]);
      }
    }

    // epilogue: d2 = (sq_i + sq_j) - 2*dot ; running top-3 per row
    int cb[4];
    cb[0] = tx*4; cb[1] = tx*4 + 2; cb[2] = 64 + tx*4; cb[3] = 64 + tx*4 + 2;
    #pragma unroll
    for (int jp = 0; jp < 4; jp++){
      int col0 = cb[jp];
      float sq0 = __ldg(&g_sq[j0c + col0]);
      float sq1 = __ldg(&g_sq[j0c + col0 + 1]);
      #pragma unroll
      for (int mi = 0; mi < 4; mi++){
        float f0, f1;
        unpack2f(acc[mi][jp], f0, f1);
        float d2a = (sqi[mi] + sq0) - 2.0f*f0;
        float d2b = (sqi[mi] + sq1) - 2.0f*f1;
        unsigned long long ka = ((unsigned long long)encf(d2a) << 32) | (unsigned)(j0c + col0);
        unsigned long long kb = ((unsigned long long)encf(d2b) << 32) | (unsigned)(j0c + col0 + 1);
        ins3(ka, best[mi][0], best[mi][1], best[mi][2]);
        ins3(kb, best[mi][0], best[mi][1], best[mi][2]);
      }
    }
    __syncthreads();
  }

  #pragma unroll
  for (int m = 0; m < 4; m++){
    int row = i0 + ty*4 + m;
    size_t base = ((size_t)(split*NN + row)*16 + tx)*3;
    g_cand[base+0] = best[m][0];
    g_cand[base+1] = best[m][1];
    g_cand[base+2] = best[m][2];
  }
}

// ---------------- k3: merge partial top-3 (warp per row) ----------------
__global__ void k_merge(){
  int g = blockIdx.x*blockDim.x + threadIdx.x;
  int row = g >> 5, lane = g & 31;
  if (row >= NN) return;
  int split = lane >> 4, tx = lane & 15;
  size_t base = ((size_t)(split*NN + row)*16 + tx)*3;
  unsigned long long b0 = g_cand[base+0];
  unsigned long long b1 = g_cand[base+1];
  unsigned long long b2 = g_cand[base+2];
  #pragma unroll
  for (int o = 16; o; o >>= 1){
    unsigned long long c0 = __shfl_xor_sync(0xffffffffu, b0, o);
    unsigned long long c1 = __shfl_xor_sync(0xffffffffu, b1, o);
    unsigned long long c2 = __shfl_xor_sync(0xffffffffu, b2, o);
    ins3(c0, b0, b1, b2);
    ins3(c1, b0, b1, b2);
    ins3(c2, b0, b1, b2);
  }
  if (lane == 0){
    g_nbr[row*3+0] = (int)(b0 & 0xffffffffull);
    g_nbr[row*3+1] = (int)(b1 & 0xffffffffull);
    g_nbr[row*3+2] = (int)(b2 & 0xffffffffull);
  }
}

// ---------------- k4: xp = x @ W (grid 128 = 64 ib x 2 heads) ----------------
__global__ __launch_bounds__(256) void k_xp(const float* __restrict__ X,
                                            const float* __restrict__ W){
  __shared__ float sA[32*129];
  __shared__ float sW[32*129];
  const float4* X4 = (const float4*)X;
  const float4* W4 = (const float4*)W;
  int tid = threadIdx.x;
  int tx = tid & 15, ty = tid >> 4;
  int ib = blockIdx.x >> 1, h = blockIdx.x & 1;
  int i0 = ib*128;
  float acc[8][8];
  #pragma unroll
  for (int a = 0; a < 8; a++)
    #pragma unroll
    for (int b = 0; b < 8; b++) acc[a][b] = 0.f;

  for (int kc = 0; kc < 4; kc++){
    __syncthreads();
    #pragma unroll
    for (int l = 0; l < 4; l++){
      int idx = tid + l*256;
      int r = idx >> 3, k4 = idx & 7;
      float4 va = X4[(i0 + r)*32 + kc*8 + k4];
      sA[(k4*4+0)*129 + r] = va.x;
      sA[(k4*4+1)*129 + r] = va.y;
      sA[(k4*4+2)*129 + r] = va.z;
      sA[(k4*4+3)*129 + r] = va.w;
      int dd = idx >> 5, c4 = idx & 31;
      float4 vw = W4[(size_t)(kc*32 + dd)*64 + h*32 + c4];
      sW[dd*129 + c4*4 + 0] = vw.x;
      sW[dd*129 + c4*4 + 1] = vw.y;
      sW[dd*129 + c4*4 + 2] = vw.z;
      sW[dd*129 + c4*4 + 3] = vw.w;
    }
    __syncthreads();
    #pragma unroll 4
    for (int k = 0; k < 32; k++){
      float a[8], b[8];
      #pragma unroll
      for (int m = 0; m < 8; m++) a[m] = sA[k*129 + ty + 16*m];
      #pragma unroll
      for (int m = 0; m < 8; m++) b[m] = sW[k*129 + tx + 16*m];
      #pragma unroll
      for (int mi = 0; mi < 8; mi++)
        #pragma unroll
        for (int mj = 0; mj < 8; mj++)
          acc[mi][mj] = fmaf(a[mi], b[mj], acc[mi][mj]);
    }
  }
  #pragma unroll
  for (int mi = 0; mi < 8; mi++)
    #pragma unroll
    for (int mj = 0; mj < 8; mj++)
      g_xp[(size_t)(i0 + ty + 16*mi)*256 + h*128 + tx + 16*mj] = acc[mi][mj];
}

// ---------------- k5: attention coeffs + init m/denom/acc ----------------
__global__ void k_attn(const float* __restrict__ att_src,
                       const float* __restrict__ att_dst){
  int g = blockIdx.x*blockDim.x + threadIdx.x;
  int n = g >> 5, lane = g & 31;
  if (n >= NN) return;
  const float4* xp4 = (const float4*)g_xp;
  float4 x0 = xp4[(size_t)n*64 + lane];
  float4 x1 = xp4[(size_t)n*64 + 32 + lane];
  const float4* s4 = (const float4*)att_src;
  const float4* d4 = (const float4*)att_dst;
  float4 a0 = s4[lane], a1 = s4[32 + lane];
  float4 c0 = d4[lane], c1 = d4[32 + lane];
  float vs0 = x0.x*a0.x + x0.y*a0.y + x0.z*a0.z + x0.w*a0.w;
  float vs1 = x1.x*a1.x + x1.y*a1.y + x1.z*a1.z + x1.w*a1.w;
  float vd0 = x0.x*c0.x + x0.y*c0.y + x0.z*c0.z + x0.w*c0.w;
  float vd1 = x1.x*c1.x + x1.y*c1.y + x1.z*c1.z + x1.w*c1.w;
  #pragma unroll
  for (int o = 16; o; o >>= 1){
    vs0 += __shfl_xor_sync(0xffffffffu, vs0, o);
    vs1 += __shfl_xor_sync(0xffffffffu, vs1, o);
    vd0 += __shfl_xor_sync(0xffffffffu, vd0, o);
    vd1 += __shfl_xor_sync(0xffffffffu, vd1, o);
  }
  if (lane == 0){
    g_as[n*2+0] = vs0; g_as[n*2+1] = vs1;
    g_ad[n*2+0] = vd0; g_ad[n*2+1] = vd1;
    g_menc[n*2+0] = 0x007FFFFFu;
    g_menc[n*2+1] = 0x007FFFFFu;
    g_denom[n*2+0] = 0.f; g_denom[n*2+1] = 0.f;
  }
  float4 z = make_float4(0.f, 0.f, 0.f, 0.f);
  ((float4*)g_acc)[(size_t)n*64 + lane] = z;
  ((float4*)g_acc)[(size_t)n*64 + 32 + lane] = z;
}

// ---------------- k6: segment max ----------------
__global__ void k_emax(){
  int idx = blockIdx.x*blockDim.x + threadIdx.x;
  if (idx >= NE*2) return;
  int e = idx >> 1, h = idx & 1;
  int s = e/3;
  int d = g_nbr[e];
  float v = g_as[s*2+h] + g_ad[d*2+h];
  v = v > 0.f ? v : 0.2f*v;
  atomicMax(&g_menc[d*2+h], encf(v));
}

// ---------------- k7: exp + segment sum ----------------
__global__ void k_esum(){
  int idx = blockIdx.x*blockDim.x + threadIdx.x;
  if (idx >= NE*2) return;
  int e = idx >> 1, h = idx & 1;
  int s = e/3;
  int d = g_nbr[e];
  float v = g_as[s*2+h] + g_ad[d*2+h];
  v = v > 0.f ? v : 0.2f*v;
  float m = decf(g_menc[d*2+h]);
  float w = __expf(v - m);
  g_w[idx] = w;
  atomicAdd(&g_denom[d*2+h], w);
}

// ---------------- k8: aggregate messages (warp per edge-head) ----------------
__global__ void k_agg(){
  int g = blockIdx.x*blockDim.x + threadIdx.x;
  int eh = g >> 5, lane = g & 31;
  if (eh >= NE*2) return;
  int e = eh >> 1, h = eh & 1;
  int s = e/3;
  int d = g_nbr[e];
  float alpha = g_w[eh] / g_denom[d*2+h];
  const float4* xp4 = (const float4*)g_xp;
  float4 v = xp4[(size_t)s*64 + h*32 + lane];
  float* dst = &g_acc[(size_t)d*256 + h*128 + lane*4];
  atomicAdd(dst+0, alpha*v.x);
  atomicAdd(dst+1, alpha*v.y);
  atomicAdd(dst+2, alpha*v.z);
  atomicAdd(dst+3, alpha*v.w);
}

// ---------------- k9: head-mean + bias + LayerNorm + ReLU + residual ----------------
__global__ void k_final(const float* __restrict__ X,
                        const float* __restrict__ bias,
                        const float* __restrict__ gamma,
                        const float* __restrict__ beta,
                        float* __restrict__ out){
  int g = blockIdx.x*blockDim.x + threadIdx.x;
  int n = g >> 5, lane = g & 31;
  if (n >= NN) return;
  float v[4];
  #pragma unroll
  for (int c = 0; c < 4; c++){
    int dd = lane*4 + c;
    float a0 = g_acc[(size_t)n*256 + dd];
    float a1 = g_acc[(size_t)n*256 + 128 + dd];
    v[c] = 0.5f*(a0 + a1) + bias[dd];
  }
  float s = v[0]+v[1]+v[2]+v[3];
  #pragma unroll
  for (int o = 16; o; o >>= 1) s += __shfl_xor_sync(0xffffffffu, s, o);
  float mu = s * (1.0f/128.0f);
  float q = 0.f;
  #pragma unroll
  for (int c = 0; c < 4; c++){ float t = v[c]-mu; q += t*t; }
  #pragma unroll
  for (int o = 16; o; o >>= 1) q += __shfl_xor_sync(0xffffffffu, q, o);
  float rstd = rsqrtf(q*(1.0f/128.0f) + 1e-5f);
  #pragma unroll
  for (int c = 0; c < 4; c++){
    int dd = lane*4 + c;
    float y = (v[c]-mu)*rstd*gamma[dd] + beta[dd];
    y = y > 0.f ? y : 0.f;
    out[(size_t)n*128 + dd] = X[(size_t)n*128 + dd] + y;
  }
}

// ---------------- launch ----------------
extern "C" void kernel_launch(void* const* d_in, const int* in_sizes, int n_in,
                              void* d_out, int out_size) {
  const float* prototypes = (const float*)d_in[0];
  // d_in[1] = labels (unused in forward)
  const float* W       = (const float*)d_in[2];
  const float* att_src = (const float*)d_in[3];
  const float* att_dst = (const float*)d_in[4];
  const float* bias    = (const float*)d_in[5];
  const float* gamma   = (const float*)d_in[6];
  const float* beta    = (const float*)d_in[7];
  float* out = (float*)d_out;

  const int KNN_SMEM = 3 * 16384 * 4;   // 192 KB dynamic smem
  cudaFuncSetAttribute(k_knn, cudaFuncAttributeMaxDynamicSharedMemorySize, KNN_SMEM);

  k_sqnorm<<<NN/8, 256>>>((const float4*)prototypes);
  k_knn<<<128, 512, KNN_SMEM>>>(prototypes);
  k_merge<<<NN/8, 256>>>();
  k_xp<<<128, 256>>>(prototypes, W);
  k_attn<<<NN/8, 256>>>(att_src, att_dst);
  k_emax<<<(NE*2+255)/256, 256>>>();
  k_esum<<<(NE*2+255)/256, 256>>>();
  k_agg<<<(NE*2*32+255)/256, 256>>>();
  k_final<<<NN/8, 256>>>(prototypes, bias, gamma, beta, out);
}